// round 4
// baseline (speedup 1.0000x reference)
#include <cuda_runtime.h>
#include <math.h>

#define NN   8192
#define NE   81920
#define NE2  1310720
#define HH   128
#define HSZ  (1 << 18)

typedef unsigned long long ull;

// ---------------- device scratch ----------------
__device__ __align__(16) float g_u[3][128];
__device__ __align__(16) float g_v[3][128];
__device__ float  g_gb;                      // gat_bias . linW
__device__ __align__(16) float4 g_nf4[NN];   // (fs, fd, fq, 0) per node
__device__ __align__(16) float4 g_ng4[NN];   // (gs, gd, gq, 0) per node
__device__ __align__(16) float4 g_aq[NE];    // (a_s, a_d, q, 0) per edge
__device__ float  g_adst[NE];                // a_d copy (dst gather)
__device__ __align__(16) float2 g_numden[NE];
__device__ unsigned g_hkey[HSZ];
__device__ __align__(16) float2 g_hval[HSZ]; // (cnt, gate-sum)
__device__ float  g_deg[NN];
__device__ __align__(16) int    g_cnt2[NN];
__device__ int    g_offs2[NN + 1];
__device__ int    g_cur2[NN];
__device__ __align__(16) int2   g_rw[NE];    // (row, w bits) col-sorted
__device__ __align__(16) float  g_h1[NN * HH];
__device__ __align__(16) float  g_h2[NN * HH];
__device__ float  g_gsum[HH];
__device__ ull    g_wp[3 * 128 * 64];        // paired W: (W[k][j], W[k][j+64])
__device__ int    g_ctr;

// ---------------- f32x2 helpers ----------------
__device__ __forceinline__ ull pack2(float v) {
    ull r; asm("mov.b64 %0, {%1, %1};" : "=l"(r) : "f"(v)); return r;
}
__device__ __forceinline__ ull pack2b(float lo, float hi) {
    ull r; asm("mov.b64 %0, {%1, %2};" : "=l"(r) : "f"(lo), "f"(hi)); return r;
}
__device__ __forceinline__ void fma2(ull& acc, ull a, ull b) {
    asm("fma.rn.f32x2 %0, %1, %2, %0;" : "+l"(acc) : "l"(a), "l"(b));
}
__device__ __forceinline__ float2 unpack2(ull v) {
    float2 r; asm("mov.b64 {%0, %1}, %2;" : "=f"(r.x), "=f"(r.y) : "l"(v)); return r;
}

// ---------------- init: zero + uv + gb + W pairing ----------------
__global__ void k_init(const float* __restrict__ gatW, const float* __restrict__ att_src,
                       const float* __restrict__ att_dst, const float* __restrict__ linW,
                       const float* __restrict__ gat_bias,
                       const float* __restrict__ W1, const float* __restrict__ W2,
                       const float* __restrict__ W3) {
    int i = blockIdx.x * blockDim.x + threadIdx.x;
    if (i < HSZ) { g_hkey[i] = 0u; g_hval[i] = make_float2(0.f, 0.f); }
    if (i < NN)  { g_cnt2[i] = 0; g_deg[i] = 0.0f; }
    if (i < HH)  g_gsum[i] = 0.0f;
    if (i == 0)  g_ctr = 0;
    if (i < 768) {
        int q = i >> 7, k = i & 127;
        const float* a = (q == 0 || q == 3) ? att_src : ((q == 1 || q == 4) ? att_dst : linW);
        int rb = ((q < 3) ? k : (128 + k)) * 64;
        float s = 0.0f;
#pragma unroll 8
        for (int j = 0; j < 64; j++) s += gatW[rb + j] * a[j];
        if (q < 3) g_u[q][k] = s; else g_v[q - 3][k] = s;
    }
    if (i < 32) {
        float gb = gat_bias[i] * linW[i] + gat_bias[i + 32] * linW[i + 32];
#pragma unroll
        for (int o = 16; o; o >>= 1) gb += __shfl_xor_sync(0xffffffffu, gb, o);
        if (i == 0) g_gb = gb;
    }
    if (i < 3 * 8192) {
        int layer = i >> 13, rem = i & 8191;
        int k = rem >> 6, jj = rem & 63;
        const float* W = (layer == 0) ? W1 : ((layer == 1) ? W2 : W3);
        g_wp[i] = pack2b(W[k * 128 + jj], W[k * 128 + jj + 64]);
    }
}

// per-node scalars: 6 dots of embed row with u/v vectors; warp per node
__global__ void k_nscal(const float* __restrict__ embed) {
    int n = blockIdx.x * 8 + (threadIdx.x >> 5);
    int l = threadIdx.x & 31;
    float4 e = *(const float4*)&embed[n * 128 + l * 4];
    float a0, a1, a2, a3, a4, a5;
    {
        float4 u;
        u = *(const float4*)&g_u[0][l * 4]; a0 = e.x*u.x + e.y*u.y + e.z*u.z + e.w*u.w;
        u = *(const float4*)&g_u[1][l * 4]; a1 = e.x*u.x + e.y*u.y + e.z*u.z + e.w*u.w;
        u = *(const float4*)&g_u[2][l * 4]; a2 = e.x*u.x + e.y*u.y + e.z*u.z + e.w*u.w;
        u = *(const float4*)&g_v[0][l * 4]; a3 = e.x*u.x + e.y*u.y + e.z*u.z + e.w*u.w;
        u = *(const float4*)&g_v[1][l * 4]; a4 = e.x*u.x + e.y*u.y + e.z*u.z + e.w*u.w;
        u = *(const float4*)&g_v[2][l * 4]; a5 = e.x*u.x + e.y*u.y + e.z*u.z + e.w*u.w;
    }
#pragma unroll
    for (int o = 16; o; o >>= 1) {
        a0 += __shfl_xor_sync(0xffffffffu, a0, o);
        a1 += __shfl_xor_sync(0xffffffffu, a1, o);
        a2 += __shfl_xor_sync(0xffffffffu, a2, o);
        a3 += __shfl_xor_sync(0xffffffffu, a3, o);
        a4 += __shfl_xor_sync(0xffffffffu, a4, o);
        a5 += __shfl_xor_sync(0xffffffffu, a5, o);
    }
    if (l == 0) {
        g_nf4[n] = make_float4(a0, a1, a2, 0.f);
        g_ng4[n] = make_float4(a3, a4, a5, 0.f);
    }
}

// per-edge scalars + numden self-loop init + col histogram
__global__ void k_edge(const int* __restrict__ ei) {
    int e = blockIdx.x * blockDim.x + threadIdx.x;
    if (e >= NE) return;
    int r = ei[e], c = ei[NE + e];
    float4 a = g_nf4[r], b = g_ng4[c];
    float as = a.x + b.x, ad = a.y + b.y, q = a.z + b.z;
    g_aq[e]   = make_float4(as, ad, q, 0.f);
    g_adst[e] = ad;
    float al = as + ad;
    al = (al > 0.0f) ? al : 0.2f * al;
    float eal = __expf(al);
    g_numden[e] = make_float2(eal * q, eal);   // self-loop contribution
    atomicAdd(&g_cnt2[c], 1);
}

// 4 extended edges per thread: one float2 atomic each -> segmented (num, den)
__global__ void k_scatter(const int* __restrict__ ne) {
    int base = (blockIdx.x * blockDim.x + threadIdx.x) * 4;
    int4 s4 = *(const int4*)&ne[base];
    int4 d4 = *(const int4*)&ne[NE2 + base];
    float4 q0 = g_aq[s4.x];
    float4 q1 = g_aq[s4.y];
    float4 q2 = g_aq[s4.z];
    float4 q3 = g_aq[s4.w];
    float b0 = g_adst[d4.x], b1 = g_adst[d4.y], b2 = g_adst[d4.z], b3 = g_adst[d4.w];
    float a0 = q0.x + b0; a0 = (a0 > 0.f) ? a0 : 0.2f * a0;
    float a1 = q1.x + b1; a1 = (a1 > 0.f) ? a1 : 0.2f * a1;
    float a2 = q2.x + b2; a2 = (a2 > 0.f) ? a2 : 0.2f * a2;
    float a3 = q3.x + b3; a3 = (a3 > 0.f) ? a3 : 0.2f * a3;
    float e0 = __expf(a0), e1 = __expf(a1), e2 = __expf(a2), e3 = __expf(a3);
    atomicAdd(&g_numden[d4.x], make_float2(e0 * q0.z, e0));
    atomicAdd(&g_numden[d4.y], make_float2(e1 * q1.z, e1));
    atomicAdd(&g_numden[d4.z], make_float2(e2 * q2.z, e2));
    atomicAdd(&g_numden[d4.w], make_float2(e3 * q3.z, e3));
}

__device__ __forceinline__ unsigned hash_key(unsigned key) {
    return ((key * 2654435761u) >> 14) & (HSZ - 1);
}

// fused: gate computation + hash insert
__global__ void k_hins(const int* __restrict__ ei, const float* __restrict__ noise,
                       const float* __restrict__ tmp, const float* __restrict__ linb) {
    int e = blockIdx.x * blockDim.x + threadIdx.x;
    if (e >= NE) return;
    float2 nd = g_numden[e];
    float la = nd.x / nd.y + g_gb + linb[0];
    float nv = noise[e];
    float xv = (__logf(nv) - log1pf(-nv) + la) / tmp[0];
    float gate = 1.0f / (1.0f + __expf(-xv));
    unsigned key = (unsigned)ei[e] * 8192u + (unsigned)ei[NE + e] + 1u;
    unsigned s = hash_key(key);
    while (true) {
        unsigned old = atomicCAS(&g_hkey[s], 0u, key);
        if (old == 0u || old == key) break;
        s = (s + 1) & (HSZ - 1);
    }
    atomicAdd(&g_hval[s], make_float2(1.0f, gate));
}

__device__ __forceinline__ int hash_find(unsigned key) {
    unsigned s = hash_key(key);
    while (true) {
        unsigned k = g_hkey[s];
        if (k == key) return (int)s;
        if (k == 0u) return -1;
        s = (s + 1) & (HSZ - 1);
    }
}

// single-block scan of g_cnt2[8192] -> offs2/cur2
__global__ void k_scan2() {
    int t = threadIdx.x;
    int base = t * 8;
    int4 v0 = *(const int4*)&g_cnt2[base];
    int4 v1 = *(const int4*)&g_cnt2[base + 4];
    int vals[8] = {v0.x, v0.y, v0.z, v0.w, v1.x, v1.y, v1.z, v1.w};
    int s = 0;
#pragma unroll
    for (int k = 0; k < 8; k++) s += vals[k];
    int x = s;
#pragma unroll
    for (int o = 1; o < 32; o <<= 1) {
        int y = __shfl_up_sync(0xffffffffu, x, o);
        if ((t & 31) >= o) x += y;
    }
    __shared__ int ws[32], wo[32];
    if ((t & 31) == 31) ws[t >> 5] = x;
    __syncthreads();
    if (t < 32) {
        int y = ws[t];
        int z = y;
#pragma unroll
        for (int o = 1; o < 32; o <<= 1) {
            int q = __shfl_up_sync(0xffffffffu, z, o);
            if (t >= o) z += q;
        }
        wo[t] = z - y;
    }
    __syncthreads();
    int p = (x - s) + wo[t >> 5];
#pragma unroll
    for (int k = 0; k < 8; k++) {
        g_offs2[base + k] = p;
        g_cur2[base + k]  = p;
        p += vals[k];
    }
    if (t == 1023) g_offs2[NN] = p;
}

// fused: edge weight via hash lookups + degree + col-sorted scatter
__global__ void k_edgew_sort2(const int* __restrict__ ei) {
    int e = blockIdx.x * blockDim.x + threadIdx.x;
    if (e >= NE) return;
    int r = ei[e], c = ei[NE + e];
    int sf = hash_find((unsigned)r * 8192u + (unsigned)c + 1u);
    float2 hv = g_hval[sf];
    int sr = hash_find((unsigned)c * 8192u + (unsigned)r + 1u);
    float srev = (sr >= 0) ? g_hval[sr].y : 0.0f;
    float em = hv.x * 0.5f * (hv.y + srev);
    float w = 1.0f / (1.0f + __expf(-em));
    atomicAdd(&g_deg[c], w);
    int pos = atomicAdd(&g_cur2[c], 1);
    g_rw[pos] = make_int2(r, __float_as_int(w));
}

// fused GCN layer: aggregate (warp per 8 nodes -> smem) then f32x2 GEMM (+relu)
// layer 2: mean-pool accumulate + fused classifier in last block
__global__ void k_gcn(const float* __restrict__ xin, int layer,
                      const float* __restrict__ Wc, float* __restrict__ out) {
    const float* xh = (layer == 0) ? xin : ((layer == 1) ? g_h1 : g_h2);
    int nb = blockIdx.x * 64;
    __shared__ __align__(16) float sa[64][128];
    int wid = threadIdx.x >> 5, l = threadIdx.x & 31;
#pragma unroll 1
    for (int mm = 0; mm < 8; mm++) {
        int m = wid * 8 + mm;
        int n = nb + m;
        int e0 = g_offs2[n], e1 = g_offs2[n + 1];
        float4 acc = make_float4(0.f, 0.f, 0.f, 0.f);
        for (int i = e0; i < e1; i++) {
            int2 rw = g_rw[i];
            float wt = __int_as_float(rw.y);
            float4 xr = *(const float4*)&xh[rw.x * 128 + l * 4];
            acc.x += wt * xr.x; acc.y += wt * xr.y; acc.z += wt * xr.z; acc.w += wt * xr.w;
        }
        float invd = 1.0f / (g_deg[n] + 1.0f);
        float4 xn = *(const float4*)&xh[n * 128 + l * 4];
        float4 t;
        t.x = (xn.x + acc.x) * invd; t.y = (xn.y + acc.y) * invd;
        t.z = (xn.z + acc.z) * invd; t.w = (xn.w + acc.w) * invd;
        *(float4*)&sa[m][l * 4] = t;
    }
    __syncthreads();

    int jj = threadIdx.x & 63;         // column pair (jj, jj+64)
    int mh = threadIdx.x >> 6;         // 16-node group
    const ull* Wp = &g_wp[layer * 8192];
    ull acc2[16];
#pragma unroll
    for (int m = 0; m < 16; m++) acc2[m] = 0ull;
#pragma unroll 1
    for (int k0 = 0; k0 < 128; k0 += 4) {
        ull w0 = Wp[(k0 + 0) * 64 + jj];
        ull w1 = Wp[(k0 + 1) * 64 + jj];
        ull w2 = Wp[(k0 + 2) * 64 + jj];
        ull w3 = Wp[(k0 + 3) * 64 + jj];
#pragma unroll
        for (int m = 0; m < 16; m++) {
            float4 a = *(const float4*)&sa[mh * 16 + m][k0];
            fma2(acc2[m], pack2(a.x), w0);
            fma2(acc2[m], pack2(a.y), w1);
            fma2(acc2[m], pack2(a.z), w2);
            fma2(acc2[m], pack2(a.w), w3);
        }
    }

    if (layer < 2) {
        float* o = layer ? g_h2 : g_h1;
#pragma unroll
        for (int m = 0; m < 16; m++) {
            float2 v = unpack2(acc2[m]);
            int node = nb + mh * 16 + m;
            o[node * 128 + jj]      = fmaxf(v.x, 0.0f);
            o[node * 128 + jj + 64] = fmaxf(v.y, 0.0f);
        }
    } else {
        float s0 = 0.0f, s1 = 0.0f;
#pragma unroll
        for (int m = 0; m < 16; m++) {
            float2 v = unpack2(acc2[m]);
            s0 += fmaxf(v.x, 0.0f);
            s1 += fmaxf(v.y, 0.0f);
        }
        atomicAdd(&g_gsum[jj], s0);
        atomicAdd(&g_gsum[jj + 64], s1);
        __threadfence();
        __shared__ int lastf;
        __syncthreads();
        if (threadIdx.x == 0) lastf = (atomicAdd(&g_ctr, 1) == (int)gridDim.x - 1) ? 1 : 0;
        __syncthreads();
        if (lastf && threadIdx.x < 32) {
            int lane = threadIdx.x;
            volatile const float* gs = g_gsum;
            float l0 = 0.0f, l1 = 0.0f;
            for (int j = lane; j < 128; j += 32) {
                float gv = gs[j] * (1.0f / 8192.0f);
                l0 += gv * Wc[j * 2 + 0];
                l1 += gv * Wc[j * 2 + 1];
            }
#pragma unroll
            for (int o = 16; o; o >>= 1) {
                l0 += __shfl_xor_sync(0xffffffffu, l0, o);
                l1 += __shfl_xor_sync(0xffffffffu, l1, o);
            }
            if (lane == 0) {
                float mx = fmaxf(l0, l1);
                float e0 = __expf(l0 - mx), e1 = __expf(l1 - mx);
                float s = e0 + e1;
                out[0] = e0 / s;
                out[1] = e1 / s;
            }
        }
    }
}

// ---------------- host launcher ----------------
extern "C" void kernel_launch(void* const* d_in, const int* in_sizes, int n_in,
                              void* d_out, int out_size) {
    const float* x        = (const float*)d_in[0];
    const float* embed    = (const float*)d_in[1];
    const float* noise    = (const float*)d_in[2];
    const float* tmp      = (const float*)d_in[3];
    const float* gatW     = (const float*)d_in[4];
    const float* att_src  = (const float*)d_in[5];
    const float* att_dst  = (const float*)d_in[6];
    const float* gat_bias = (const float*)d_in[7];
    const float* linW     = (const float*)d_in[8];
    const float* linb     = (const float*)d_in[9];
    const float* W1       = (const float*)d_in[10];
    const float* W2       = (const float*)d_in[11];
    const float* W3       = (const float*)d_in[12];
    const float* Wc       = (const float*)d_in[13];
    const int*   ei       = (const int*)d_in[14];
    const int*   ne       = (const int*)d_in[15];
    float* out = (float*)d_out;

    k_init<<<HSZ / 256, 256>>>(gatW, att_src, att_dst, linW, gat_bias, W1, W2, W3);
    k_nscal<<<NN / 8, 256>>>(embed);
    k_edge<<<NE / 256, 256>>>(ei);
    k_scatter<<<NE2 / 1024, 256>>>(ne);
    k_hins<<<NE / 256, 256>>>(ei, noise, tmp, linb);
    k_scan2<<<1, 1024>>>();
    k_edgew_sort2<<<NE / 256, 256>>>(ei);

    k_gcn<<<NN / 64, 256>>>(x, 0, Wc, out);
    k_gcn<<<NN / 64, 256>>>(x, 1, Wc, out);
    k_gcn<<<NN / 64, 256>>>(x, 2, Wc, out);
}

// round 5
// speedup vs baseline: 1.0419x; 1.0419x over previous
#include <cuda_runtime.h>
#include <math.h>

#define NN   8192
#define NE   81920
#define NE2  1310720
#define HH   128
#define HSZ  (1 << 18)

typedef unsigned long long ull;

// ---------------- device scratch ----------------
__device__ __align__(16) float g_u[3][128];
__device__ __align__(16) float g_v[3][128];
__device__ float  g_gb;                      // gat_bias . linW
__device__ __align__(16) float4 g_nf4[NN];   // (fs, fd, fq, 0) per node
__device__ __align__(16) float4 g_ng4[NN];   // (gs, gd, gq, 0) per node
__device__ __align__(16) float4 g_srcv[NE];  // (a_s, e^{a_s}, e^{.2 a_s}, q)
__device__ __align__(16) float4 g_dstv[NE];  // (a_d, e^{a_d}, e^{.2 a_d}, 0)
__device__ __align__(16) float2 g_numden[NE];
__device__ unsigned g_hkey[HSZ];
__device__ __align__(16) float2 g_hval[HSZ]; // (cnt, gate-sum)
__device__ float  g_deg[NN];
__device__ __align__(16) int    g_cnt2[NN];
__device__ int    g_offs2[NN + 1];
__device__ int    g_cur2[NN];
__device__ __align__(16) int2   g_rw[NE];    // (row, w bits) col-sorted
__device__ __align__(16) float  g_t[NN * HH];
__device__ __align__(16) float  g_h1[NN * HH];
__device__ __align__(16) float  g_h2[NN * HH];
__device__ float  g_gsum[HH];
__device__ ull    g_wp[3 * 128 * 64];        // paired W: (W[k][j], W[k][j+64])
__device__ int    g_ctr;

// ---------------- f32x2 helpers ----------------
__device__ __forceinline__ ull pack2(float v) {
    ull r; asm("mov.b64 %0, {%1, %1};" : "=l"(r) : "f"(v)); return r;
}
__device__ __forceinline__ ull pack2b(float lo, float hi) {
    ull r; asm("mov.b64 %0, {%1, %2};" : "=l"(r) : "f"(lo), "f"(hi)); return r;
}
__device__ __forceinline__ void fma2(ull& acc, ull a, ull b) {
    asm("fma.rn.f32x2 %0, %1, %2, %0;" : "+l"(acc) : "l"(a), "l"(b));
}
__device__ __forceinline__ float2 unpack2(ull v) {
    float2 r; asm("mov.b64 {%0, %1}, %2;" : "=f"(r.x), "=f"(r.y) : "l"(v)); return r;
}

// ---------------- init: zero + uv + gb + W pairing ----------------
__global__ void k_init(const float* __restrict__ gatW, const float* __restrict__ att_src,
                       const float* __restrict__ att_dst, const float* __restrict__ linW,
                       const float* __restrict__ gat_bias,
                       const float* __restrict__ W1, const float* __restrict__ W2,
                       const float* __restrict__ W3) {
    int i = blockIdx.x * blockDim.x + threadIdx.x;
    if (i < HSZ) { g_hkey[i] = 0u; g_hval[i] = make_float2(0.f, 0.f); }
    if (i < NN)  { g_cnt2[i] = 0; g_deg[i] = 0.0f; }
    if (i < HH)  g_gsum[i] = 0.0f;
    if (i == 0)  g_ctr = 0;
    if (i < 768) {
        int q = i >> 7, k = i & 127;
        const float* a = (q == 0 || q == 3) ? att_src : ((q == 1 || q == 4) ? att_dst : linW);
        int rb = ((q < 3) ? k : (128 + k)) * 64;
        float s = 0.0f;
#pragma unroll 8
        for (int j = 0; j < 64; j++) s += gatW[rb + j] * a[j];
        if (q < 3) g_u[q][k] = s; else g_v[q - 3][k] = s;
    }
    if (i < 32) {
        float gb = gat_bias[i] * linW[i] + gat_bias[i + 32] * linW[i + 32];
#pragma unroll
        for (int o = 16; o; o >>= 1) gb += __shfl_xor_sync(0xffffffffu, gb, o);
        if (i == 0) g_gb = gb;
    }
    if (i < 3 * 8192) {
        int layer = i >> 13, rem = i & 8191;
        int k = rem >> 6, jj = rem & 63;
        const float* W = (layer == 0) ? W1 : ((layer == 1) ? W2 : W3);
        g_wp[i] = pack2b(W[k * 128 + jj], W[k * 128 + jj + 64]);
    }
}

// per-node scalars: 6 dots of embed row with u/v vectors; warp per node
__global__ void k_nscal(const float* __restrict__ embed) {
    int n = blockIdx.x * 8 + (threadIdx.x >> 5);
    int l = threadIdx.x & 31;
    float4 e = *(const float4*)&embed[n * 128 + l * 4];
    float a0, a1, a2, a3, a4, a5;
    {
        float4 u;
        u = *(const float4*)&g_u[0][l * 4]; a0 = e.x*u.x + e.y*u.y + e.z*u.z + e.w*u.w;
        u = *(const float4*)&g_u[1][l * 4]; a1 = e.x*u.x + e.y*u.y + e.z*u.z + e.w*u.w;
        u = *(const float4*)&g_u[2][l * 4]; a2 = e.x*u.x + e.y*u.y + e.z*u.z + e.w*u.w;
        u = *(const float4*)&g_v[0][l * 4]; a3 = e.x*u.x + e.y*u.y + e.z*u.z + e.w*u.w;
        u = *(const float4*)&g_v[1][l * 4]; a4 = e.x*u.x + e.y*u.y + e.z*u.z + e.w*u.w;
        u = *(const float4*)&g_v[2][l * 4]; a5 = e.x*u.x + e.y*u.y + e.z*u.z + e.w*u.w;
    }
#pragma unroll
    for (int o = 16; o; o >>= 1) {
        a0 += __shfl_xor_sync(0xffffffffu, a0, o);
        a1 += __shfl_xor_sync(0xffffffffu, a1, o);
        a2 += __shfl_xor_sync(0xffffffffu, a2, o);
        a3 += __shfl_xor_sync(0xffffffffu, a3, o);
        a4 += __shfl_xor_sync(0xffffffffu, a4, o);
        a5 += __shfl_xor_sync(0xffffffffu, a5, o);
    }
    if (l == 0) {
        g_nf4[n] = make_float4(a0, a1, a2, 0.f);
        g_ng4[n] = make_float4(a3, a4, a5, 0.f);
    }
}

// per-edge scalars + exp factors + numden self-loop init + col histogram
__global__ void k_edge(const int* __restrict__ ei) {
    int e = blockIdx.x * blockDim.x + threadIdx.x;
    if (e >= NE) return;
    int r = ei[e], c = ei[NE + e];
    float4 a = g_nf4[r], b = g_ng4[c];
    float as = a.x + b.x, ad = a.y + b.y, q = a.z + b.z;
    float es  = __expf(as),        ed  = __expf(ad);
    float es2 = __expf(0.2f * as), ed2 = __expf(0.2f * ad);
    g_srcv[e] = make_float4(as, es, es2, q);
    g_dstv[e] = make_float4(ad, ed, ed2, 0.f);
    float sum = as + ad;
    float eal = (sum > 0.0f) ? es * ed : es2 * ed2;    // self-loop
    g_numden[e] = make_float2(eal * q, eal);
    atomicAdd(&g_cnt2[c], 1);
}

// 4 extended edges per thread: gather factors, select branch, one float2 RED each
__global__ void k_scatter(const int* __restrict__ ne) {
    int base = (blockIdx.x * blockDim.x + threadIdx.x) * 4;
    int4 s4 = *(const int4*)&ne[base];
    int4 d4 = *(const int4*)&ne[NE2 + base];
    int s[4] = {s4.x, s4.y, s4.z, s4.w};
    int d[4] = {d4.x, d4.y, d4.z, d4.w};
    float4 sv[4], dv[4];
#pragma unroll
    for (int k = 0; k < 4; k++) { sv[k] = g_srcv[s[k]]; dv[k] = g_dstv[d[k]]; }
#pragma unroll
    for (int k = 0; k < 4; k++) {
        float a = sv[k].x + dv[k].x;
        float eal = (a > 0.0f) ? sv[k].y * dv[k].y : sv[k].z * dv[k].z;
        atomicAdd(&g_numden[d[k]], make_float2(eal * sv[k].w, eal));
    }
}

__device__ __forceinline__ unsigned hash_key(unsigned key) {
    return ((key * 2654435761u) >> 14) & (HSZ - 1);
}

// fused: gate computation + hash insert
__global__ void k_hins(const int* __restrict__ ei, const float* __restrict__ noise,
                       const float* __restrict__ tmp, const float* __restrict__ linb) {
    int e = blockIdx.x * blockDim.x + threadIdx.x;
    if (e >= NE) return;
    float2 nd = g_numden[e];
    float la = nd.x / nd.y + g_gb + linb[0];
    float nv = noise[e];
    float xv = (__logf(nv) - log1pf(-nv) + la) / tmp[0];
    float gate = 1.0f / (1.0f + __expf(-xv));
    unsigned key = (unsigned)ei[e] * 8192u + (unsigned)ei[NE + e] + 1u;
    unsigned s = hash_key(key);
    while (true) {
        unsigned old = atomicCAS(&g_hkey[s], 0u, key);
        if (old == 0u || old == key) break;
        s = (s + 1) & (HSZ - 1);
    }
    atomicAdd(&g_hval[s], make_float2(1.0f, gate));
}

__device__ __forceinline__ int hash_find(unsigned key) {
    unsigned s = hash_key(key);
    while (true) {
        unsigned k = g_hkey[s];
        if (k == key) return (int)s;
        if (k == 0u) return -1;
        s = (s + 1) & (HSZ - 1);
    }
}

// single-block scan of g_cnt2[8192] -> offs2/cur2
__global__ void k_scan2() {
    int t = threadIdx.x;
    int base = t * 8;
    int4 v0 = *(const int4*)&g_cnt2[base];
    int4 v1 = *(const int4*)&g_cnt2[base + 4];
    int vals[8] = {v0.x, v0.y, v0.z, v0.w, v1.x, v1.y, v1.z, v1.w};
    int s = 0;
#pragma unroll
    for (int k = 0; k < 8; k++) s += vals[k];
    int x = s;
#pragma unroll
    for (int o = 1; o < 32; o <<= 1) {
        int y = __shfl_up_sync(0xffffffffu, x, o);
        if ((t & 31) >= o) x += y;
    }
    __shared__ int ws[32], wo[32];
    if ((t & 31) == 31) ws[t >> 5] = x;
    __syncthreads();
    if (t < 32) {
        int y = ws[t];
        int z = y;
#pragma unroll
        for (int o = 1; o < 32; o <<= 1) {
            int q = __shfl_up_sync(0xffffffffu, z, o);
            if (t >= o) z += q;
        }
        wo[t] = z - y;
    }
    __syncthreads();
    int p = (x - s) + wo[t >> 5];
#pragma unroll
    for (int k = 0; k < 8; k++) {
        g_offs2[base + k] = p;
        g_cur2[base + k]  = p;
        p += vals[k];
    }
    if (t == 1023) g_offs2[NN] = p;
}

// fused: edge weight via hash lookups + degree + col-sorted scatter
__global__ void k_edgew_sort2(const int* __restrict__ ei) {
    int e = blockIdx.x * blockDim.x + threadIdx.x;
    if (e >= NE) return;
    int r = ei[e], c = ei[NE + e];
    int sf = hash_find((unsigned)r * 8192u + (unsigned)c + 1u);
    float2 hv = g_hval[sf];
    int sr = hash_find((unsigned)c * 8192u + (unsigned)r + 1u);
    float srev = (sr >= 0) ? g_hval[sr].y : 0.0f;
    float em = hv.x * 0.5f * (hv.y + srev);
    float w = 1.0f / (1.0f + __expf(-em));
    atomicAdd(&g_deg[c], w);
    int pos = atomicAdd(&g_cur2[c], 1);
    g_rw[pos] = make_int2(r, __float_as_int(w));
}

// GCN aggregate: warp per node -> g_t  (1024 blocks: latency well hidden)
__global__ void k_agg(const float* __restrict__ xin, int layer) {
    const float* xh = (layer == 0) ? xin : ((layer == 1) ? g_h1 : g_h2);
    int n = blockIdx.x * 8 + (threadIdx.x >> 5);
    int l = threadIdx.x & 31;
    int e0 = g_offs2[n], e1 = g_offs2[n + 1];
    float4 acc = make_float4(0.f, 0.f, 0.f, 0.f);
    for (int i = e0; i < e1; i++) {
        int2 rw = g_rw[i];
        float wt = __int_as_float(rw.y);
        float4 xr = *(const float4*)&xh[rw.x * 128 + l * 4];
        acc.x += wt * xr.x; acc.y += wt * xr.y; acc.z += wt * xr.z; acc.w += wt * xr.w;
    }
    float invd = 1.0f / (g_deg[n] + 1.0f);
    float4 xn = *(const float4*)&xh[n * 128 + l * 4];
    float4 t;
    t.x = (xn.x + acc.x) * invd; t.y = (xn.y + acc.y) * invd;
    t.z = (xn.z + acc.z) * invd; t.w = (xn.w + acc.w) * invd;
    *(float4*)&g_t[n * 128 + l * 4] = t;
}

// GEMM: out = relu(g_t @ W) via f32x2; 64 nodes/block; layer 2 fuses pool+classifier
__global__ void k_mm(int layer, const float* __restrict__ Wc, float* __restrict__ out) {
    int nb = blockIdx.x * 64;
    __shared__ __align__(16) float sa[64][128];
    {
        const float4* src = (const float4*)&g_t[nb * 128];
        float4* dst = (float4*)sa;
#pragma unroll
        for (int i = 0; i < 8; i++) dst[threadIdx.x + i * 256] = src[threadIdx.x + i * 256];
    }
    __syncthreads();

    int jj = threadIdx.x & 63;         // column pair (jj, jj+64)
    int mh = threadIdx.x >> 6;         // 16-node group
    const ull* Wp = &g_wp[layer * 8192];
    ull acc2[16];
#pragma unroll
    for (int m = 0; m < 16; m++) acc2[m] = 0ull;
#pragma unroll 1
    for (int k0 = 0; k0 < 128; k0 += 4) {
        ull w0 = Wp[(k0 + 0) * 64 + jj];
        ull w1 = Wp[(k0 + 1) * 64 + jj];
        ull w2 = Wp[(k0 + 2) * 64 + jj];
        ull w3 = Wp[(k0 + 3) * 64 + jj];
#pragma unroll
        for (int m = 0; m < 16; m++) {
            float4 a = *(const float4*)&sa[mh * 16 + m][k0];
            fma2(acc2[m], pack2(a.x), w0);
            fma2(acc2[m], pack2(a.y), w1);
            fma2(acc2[m], pack2(a.z), w2);
            fma2(acc2[m], pack2(a.w), w3);
        }
    }

    if (layer < 2) {
        float* o = layer ? g_h2 : g_h1;
#pragma unroll
        for (int m = 0; m < 16; m++) {
            float2 v = unpack2(acc2[m]);
            int node = nb + mh * 16 + m;
            o[node * 128 + jj]      = fmaxf(v.x, 0.0f);
            o[node * 128 + jj + 64] = fmaxf(v.y, 0.0f);
        }
    } else {
        float s0 = 0.0f, s1 = 0.0f;
#pragma unroll
        for (int m = 0; m < 16; m++) {
            float2 v = unpack2(acc2[m]);
            s0 += fmaxf(v.x, 0.0f);
            s1 += fmaxf(v.y, 0.0f);
        }
        atomicAdd(&g_gsum[jj], s0);
        atomicAdd(&g_gsum[jj + 64], s1);
        __threadfence();
        __shared__ int lastf;
        __syncthreads();
        if (threadIdx.x == 0) lastf = (atomicAdd(&g_ctr, 1) == (int)gridDim.x - 1) ? 1 : 0;
        __syncthreads();
        if (lastf && threadIdx.x < 32) {
            int lane = threadIdx.x;
            volatile const float* gs = g_gsum;
            float l0 = 0.0f, l1 = 0.0f;
            for (int j = lane; j < 128; j += 32) {
                float gv = gs[j] * (1.0f / 8192.0f);
                l0 += gv * Wc[j * 2 + 0];
                l1 += gv * Wc[j * 2 + 1];
            }
#pragma unroll
            for (int o = 16; o; o >>= 1) {
                l0 += __shfl_xor_sync(0xffffffffu, l0, o);
                l1 += __shfl_xor_sync(0xffffffffu, l1, o);
            }
            if (lane == 0) {
                float mx = fmaxf(l0, l1);
                float e0 = __expf(l0 - mx), e1 = __expf(l1 - mx);
                float s = e0 + e1;
                out[0] = e0 / s;
                out[1] = e1 / s;
            }
        }
    }
}

// ---------------- host launcher ----------------
extern "C" void kernel_launch(void* const* d_in, const int* in_sizes, int n_in,
                              void* d_out, int out_size) {
    const float* x        = (const float*)d_in[0];
    const float* embed    = (const float*)d_in[1];
    const float* noise    = (const float*)d_in[2];
    const float* tmp      = (const float*)d_in[3];
    const float* gatW     = (const float*)d_in[4];
    const float* att_src  = (const float*)d_in[5];
    const float* att_dst  = (const float*)d_in[6];
    const float* gat_bias = (const float*)d_in[7];
    const float* linW     = (const float*)d_in[8];
    const float* linb     = (const float*)d_in[9];
    const float* W1       = (const float*)d_in[10];
    const float* W2       = (const float*)d_in[11];
    const float* W3       = (const float*)d_in[12];
    const float* Wc       = (const float*)d_in[13];
    const int*   ei       = (const int*)d_in[14];
    const int*   ne       = (const int*)d_in[15];
    float* out = (float*)d_out;

    k_init<<<HSZ / 256, 256>>>(gatW, att_src, att_dst, linW, gat_bias, W1, W2, W3);
    k_nscal<<<NN / 8, 256>>>(embed);
    k_edge<<<NE / 256, 256>>>(ei);
    k_scatter<<<NE2 / 1024, 256>>>(ne);
    k_hins<<<NE / 256, 256>>>(ei, noise, tmp, linb);
    k_scan2<<<1, 1024>>>();
    k_edgew_sort2<<<NE / 256, 256>>>(ei);

    k_agg<<<NN / 8, 256>>>(x, 0);
    k_mm<<<NN / 64, 256>>>(0, Wc, out);
    k_agg<<<NN / 8, 256>>>(x, 1);
    k_mm<<<NN / 64, 256>>>(1, Wc, out);
    k_agg<<<NN / 8, 256>>>(x, 2);
    k_mm<<<NN / 64, 256>>>(2, Wc, out);
}